// round 2
// baseline (speedup 1.0000x reference)
#include <cuda_runtime.h>

#define N_PTS 65536
#define N_NODES 4096
#define KSEL 20
#define IN_STRIDE 35
#define HALF_N 2048
#define CAND_CAP 24

__device__ float4 g_nodes4[N_NODES];      // (vx, vy, vz, |v|^2)
__device__ float4 g_rec[N_NODES * 4];     // R[0..8], g+t, g

__global__ void prep_kernel(const float* __restrict__ vd, const float* __restrict__ R,
                            const float* __restrict__ g, const float* __restrict__ t) {
    int j = blockIdx.x * blockDim.x + threadIdx.x;
    if (j >= N_NODES) return;
    float vx = vd[j*3+0], vy = vd[j*3+1], vz = vd[j*3+2];
    g_nodes4[j] = make_float4(vx, vy, vz, fmaf(vx,vx,fmaf(vy,vy,vz*vz)));
    const float* Rj = R + j*9;
    float g0 = g[j*3+0], g1 = g[j*3+1], g2 = g[j*3+2];
    float gt0 = g0 + t[j*3+0], gt1 = g1 + t[j*3+1], gt2 = g2 + t[j*3+2];
    g_rec[j*4+0] = make_float4(Rj[0], Rj[1], Rj[2], Rj[3]);
    g_rec[j*4+1] = make_float4(Rj[4], Rj[5], Rj[6], Rj[7]);
    g_rec[j*4+2] = make_float4(Rj[8], gt0, gt1, gt2);
    g_rec[j*4+3] = make_float4(g0, g1, g2, 0.0f);
}

__global__ void __launch_bounds__(256) dg_kernel(const float* __restrict__ inputs,
                                                 float* __restrict__ out) {
    __shared__ float4 sn[HALF_N];   // 32 KB
    const int pt = blockIdx.x * 256 + threadIdx.x;
    const float* pr = inputs + (long)pt * IN_STRIDE;
    const float px = pr[0], py = pr[1], pz = pr[2];
    const float pp = fmaf(px, px, fmaf(py, py, pz * pz));
    const float a = -2.0f * px, b = -2.0f * py, c = -2.0f * pz;

    // ---- Pass 1: top-20 smallest scores s = |v|^2 - 2 p.v (distances only) ----
    float d[KSEL];
    #pragma unroll
    for (int k = 0; k < KSEL; k++) d[k] = 3.0e38f;

    for (int half = 0; half < 2; half++) {
        __syncthreads();
        #pragma unroll
        for (int i = threadIdx.x; i < HALF_N; i += 256)
            sn[i] = g_nodes4[half * HALF_N + i];
        __syncthreads();
        #pragma unroll 4
        for (int j = 0; j < HALF_N; j++) {
            float4 v = sn[j];
            float s = fmaf(a, v.x, fmaf(b, v.y, fmaf(c, v.z, v.w)));
            if (__any_sync(0xffffffffu, s < d[KSEL-1])) {
                // branch-free sorted insert: no-op for lanes with s >= d[19]
                #pragma unroll
                for (int k = KSEL-1; k >= 1; --k)
                    d[k] = fminf(d[k], fmaxf(d[k-1], s));
                d[0] = fminf(d[0], s);
            }
        }
    }

    const float T = d[KSEL-1];
    const float dis0 = d[0] + pp;
    const float dismax = T + pp;
    const float rcpmax = 1.0f / dismax;

    // ---- Pass 2: collect candidate indices with s <= T (ties at T have w == 0) ----
    int   ids[CAND_CAP];
    float ss [CAND_CAP];
    int cnt = 0;
    for (int half = 0; half < 2; half++) {
        __syncthreads();
        #pragma unroll
        for (int i = threadIdx.x; i < HALF_N; i += 256)
            sn[i] = g_nodes4[half * HALF_N + i];
        __syncthreads();
        #pragma unroll 4
        for (int j = 0; j < HALF_N; j++) {
            float4 v = sn[j];
            float s = fmaf(a, v.x, fmaf(b, v.y, fmaf(c, v.z, v.w)));
            if (s <= T && cnt < CAND_CAP) {
                ids[cnt] = half * HALF_N + j;
                ss[cnt]  = s;
                cnt++;
            }
        }
    }

    // ---- Phase 3: gather node records, weight, blend ----
    float wsum = 0.0f, pb0 = 0.0f, pb1 = 0.0f, pb2 = 0.0f;
    float rb[9];
    #pragma unroll
    for (int i = 0; i < 9; i++) rb[i] = 0.0f;

    for (int k = 0; k < cnt; k++) {
        int j = ids[k];
        float dis = ss[k] + pp;
        float u = 1.0f - dis * rcpmax;
        float w = u * u;
        const float4* rec = g_rec + j * 4;
        float4 r0 = __ldg(rec + 0);   // R0 R1 R2 R3
        float4 r1 = __ldg(rec + 1);   // R4 R5 R6 R7
        float4 r2 = __ldg(rec + 2);   // R8 gt0 gt1 gt2
        float4 r3 = __ldg(rec + 3);   // g0 g1 g2 pad
        float y0 = px - r2.y, y1 = py - r2.z, y2 = pz - r2.w;
        // q_i = sum_j R[j*3+i] * y_j + g_i   (R^T x + g)
        float q0 = fmaf(r0.x, y0, fmaf(r0.w, y1, fmaf(r1.z, y2, r3.x)));
        float q1 = fmaf(r0.y, y0, fmaf(r1.x, y1, fmaf(r1.w, y2, r3.y)));
        float q2 = fmaf(r0.z, y0, fmaf(r1.y, y1, fmaf(r2.x, y2, r3.z)));
        wsum += w;
        pb0 = fmaf(w, q0, pb0);
        pb1 = fmaf(w, q1, pb1);
        pb2 = fmaf(w, q2, pb2);
        // R_blend[i*3+j] += w * R[j*3+i]  (R transpose)
        rb[0] = fmaf(w, r0.x, rb[0]);
        rb[1] = fmaf(w, r0.w, rb[1]);
        rb[2] = fmaf(w, r1.z, rb[2]);
        rb[3] = fmaf(w, r0.y, rb[3]);
        rb[4] = fmaf(w, r1.x, rb[4]);
        rb[5] = fmaf(w, r1.w, rb[5]);
        rb[6] = fmaf(w, r0.z, rb[6]);
        rb[7] = fmaf(w, r1.y, rb[7]);
        rb[8] = fmaf(w, r2.x, rb[8]);
    }

    const float inv = 1.0f / wsum;
    float o0 = (dis0 > 0.00021f) ? 1000000000.0f : pb0 * inv;
    float* op = out + (long)pt * 3;
    op[0] = o0;
    op[1] = pb1 * inv;
    op[2] = pb2 * inv;
    float* orr = out + (long)N_PTS * 3 + (long)pt * 9;
    #pragma unroll
    for (int i = 0; i < 9; i++) orr[i] = rb[i] * inv;
}

extern "C" void kernel_launch(void* const* d_in, const int* in_sizes, int n_in,
                              void* d_out, int out_size) {
    const float* inputs = (const float*)d_in[0];
    const float* vd     = (const float*)d_in[1];
    const float* R      = (const float*)d_in[2];
    const float* g      = (const float*)d_in[3];
    const float* t      = (const float*)d_in[4];
    float* out = (float*)d_out;

    prep_kernel<<<(N_NODES + 255) / 256, 256>>>(vd, R, g, t);
    dg_kernel<<<N_PTS / 256, 256>>>(inputs, out);
}

// round 3
// speedup vs baseline: 1.4872x; 1.4872x over previous
#include <cuda_runtime.h>

#define N_PTS 65536
#define N_NODES 4096
#define KSEL 20
#define IN_STRIDE 35
#define CHUNK_N 1024
#define CAND_CAP 24
#define NBINS 4096

__device__ float4 g_nodes4[N_NODES];      // (vx, vy, vz, |v|^2)
__device__ float4 g_rec[N_NODES * 4];     // R[0..8], g+t, g
__device__ int    g_binCount[NBINS];
__device__ int    g_binCursor[NBINS];
__device__ int    g_cell[N_PTS];
__device__ int    g_perm[N_PTS];

__global__ void prep_kernel(const float* __restrict__ vd, const float* __restrict__ R,
                            const float* __restrict__ g, const float* __restrict__ t) {
    int j = blockIdx.x * blockDim.x + threadIdx.x;
    if (j >= N_NODES) return;
    float vx = vd[j*3+0], vy = vd[j*3+1], vz = vd[j*3+2];
    g_nodes4[j] = make_float4(vx, vy, vz, fmaf(vx,vx,fmaf(vy,vy,vz*vz)));
    const float* Rj = R + j*9;
    float g0 = g[j*3+0], g1 = g[j*3+1], g2 = g[j*3+2];
    float gt0 = g0 + t[j*3+0], gt1 = g1 + t[j*3+1], gt2 = g2 + t[j*3+2];
    g_rec[j*4+0] = make_float4(Rj[0], Rj[1], Rj[2], Rj[3]);
    g_rec[j*4+1] = make_float4(Rj[4], Rj[5], Rj[6], Rj[7]);
    g_rec[j*4+2] = make_float4(Rj[8], gt0, gt1, gt2);
    g_rec[j*4+3] = make_float4(g0, g1, g2, 0.0f);
}

__device__ __forceinline__ unsigned expand3(unsigned v) {
    // 4 bits -> every 3rd bit position
    return (v & 1u) | ((v & 2u) << 2) | ((v & 4u) << 4) | ((v & 8u) << 6);
}

__device__ __forceinline__ int quant4(float x) {
    int q = (int)((x + 3.0f) * (16.0f / 6.0f));
    return q < 0 ? 0 : (q > 15 ? 15 : q);
}

__global__ void zero_bins_kernel() {
    int i = blockIdx.x * blockDim.x + threadIdx.x;
    if (i < NBINS) g_binCount[i] = 0;
}

__global__ void bin_count_kernel(const float* __restrict__ inputs) {
    int pt = blockIdx.x * blockDim.x + threadIdx.x;
    if (pt >= N_PTS) return;
    const float* pr = inputs + (long)pt * IN_STRIDE;
    unsigned code = expand3(quant4(pr[0])) | (expand3(quant4(pr[1])) << 1)
                  | (expand3(quant4(pr[2])) << 2);
    g_cell[pt] = (int)code;
    atomicAdd(&g_binCount[code], 1);
}

__global__ void scan_bins_kernel() {
    __shared__ int ssum[1024];
    int tid = threadIdx.x;
    int base = tid * 4;
    int c0 = g_binCount[base], c1 = g_binCount[base+1];
    int c2 = g_binCount[base+2], c3 = g_binCount[base+3];
    ssum[tid] = c0 + c1 + c2 + c3;
    __syncthreads();
    for (int off = 1; off < 1024; off <<= 1) {
        int v = ssum[tid];
        int add = (tid >= off) ? ssum[tid - off] : 0;
        __syncthreads();
        ssum[tid] = v + add;
        __syncthreads();
    }
    int excl = (tid > 0) ? ssum[tid - 1] : 0;
    g_binCursor[base]   = excl;
    g_binCursor[base+1] = excl + c0;
    g_binCursor[base+2] = excl + c0 + c1;
    g_binCursor[base+3] = excl + c0 + c1 + c2;
}

__global__ void scatter_kernel() {
    int pt = blockIdx.x * blockDim.x + threadIdx.x;
    if (pt >= N_PTS) return;
    int pos = atomicAdd(&g_binCursor[g_cell[pt]], 1);
    g_perm[pos] = pt;
}

__global__ void __launch_bounds__(128) dg_kernel(const float* __restrict__ inputs,
                                                 float* __restrict__ out) {
    __shared__ float4 sn[CHUNK_N];   // 16 KB
    const int pt = g_perm[blockIdx.x * 128 + threadIdx.x];
    const float* pr = inputs + (long)pt * IN_STRIDE;
    const float px = pr[0], py = pr[1], pz = pr[2];
    const float pp = fmaf(px, px, fmaf(py, py, pz * pz));
    const float a = -2.0f * px, b = -2.0f * py, c = -2.0f * pz;

    // ---- Pass 1: top-20 smallest scores s = |v|^2 - 2 p.v (distances only) ----
    float d[KSEL];
    #pragma unroll
    for (int k = 0; k < KSEL; k++) d[k] = 3.0e38f;

    for (int ch = 0; ch < N_NODES / CHUNK_N; ch++) {
        __syncthreads();
        #pragma unroll
        for (int i = threadIdx.x; i < CHUNK_N; i += 128)
            sn[i] = g_nodes4[ch * CHUNK_N + i];
        __syncthreads();
        #pragma unroll 4
        for (int j = 0; j < CHUNK_N; j++) {
            float4 v = sn[j];
            float s = fmaf(a, v.x, fmaf(b, v.y, fmaf(c, v.z, v.w)));
            if (__any_sync(0xffffffffu, s < d[KSEL-1])) {
                // branch-free sorted insert: no-op for lanes with s >= d[19]
                #pragma unroll
                for (int k = KSEL-1; k >= 1; --k)
                    d[k] = fminf(d[k], fmaxf(d[k-1], s));
                d[0] = fminf(d[0], s);
            }
        }
    }

    const float T = d[KSEL-1];
    const float dis0 = d[0] + pp;
    const float dismax = T + pp;
    const float rcpmax = 1.0f / dismax;

    // ---- Pass 2: collect candidate indices with s <= T (ties at T have w == 0) ----
    int   ids[CAND_CAP];
    float ss [CAND_CAP];
    int cnt = 0;
    for (int ch = 0; ch < N_NODES / CHUNK_N; ch++) {
        __syncthreads();
        #pragma unroll
        for (int i = threadIdx.x; i < CHUNK_N; i += 128)
            sn[i] = g_nodes4[ch * CHUNK_N + i];
        __syncthreads();
        #pragma unroll 4
        for (int j = 0; j < CHUNK_N; j++) {
            float4 v = sn[j];
            float s = fmaf(a, v.x, fmaf(b, v.y, fmaf(c, v.z, v.w)));
            if (s <= T && cnt < CAND_CAP) {
                ids[cnt] = ch * CHUNK_N + j;
                ss[cnt]  = s;
                cnt++;
            }
        }
    }

    // ---- Phase 3: gather node records, weight, blend ----
    float wsum = 0.0f, pb0 = 0.0f, pb1 = 0.0f, pb2 = 0.0f;
    float rb[9];
    #pragma unroll
    for (int i = 0; i < 9; i++) rb[i] = 0.0f;

    for (int k = 0; k < cnt; k++) {
        int j = ids[k];
        float dis = ss[k] + pp;
        float u = 1.0f - dis * rcpmax;
        float w = u * u;
        const float4* rec = g_rec + j * 4;
        float4 r0 = __ldg(rec + 0);   // R0 R1 R2 R3
        float4 r1 = __ldg(rec + 1);   // R4 R5 R6 R7
        float4 r2 = __ldg(rec + 2);   // R8 gt0 gt1 gt2
        float4 r3 = __ldg(rec + 3);   // g0 g1 g2 pad
        float y0 = px - r2.y, y1 = py - r2.z, y2 = pz - r2.w;
        // q_i = sum_j R[j*3+i] * y_j + g_i   (R^T x + g)
        float q0 = fmaf(r0.x, y0, fmaf(r0.w, y1, fmaf(r1.z, y2, r3.x)));
        float q1 = fmaf(r0.y, y0, fmaf(r1.x, y1, fmaf(r1.w, y2, r3.y)));
        float q2 = fmaf(r0.z, y0, fmaf(r1.y, y1, fmaf(r2.x, y2, r3.z)));
        wsum += w;
        pb0 = fmaf(w, q0, pb0);
        pb1 = fmaf(w, q1, pb1);
        pb2 = fmaf(w, q2, pb2);
        // R_blend[i*3+j] += w * R[j*3+i]  (R transpose)
        rb[0] = fmaf(w, r0.x, rb[0]);
        rb[1] = fmaf(w, r0.w, rb[1]);
        rb[2] = fmaf(w, r1.z, rb[2]);
        rb[3] = fmaf(w, r0.y, rb[3]);
        rb[4] = fmaf(w, r1.x, rb[4]);
        rb[5] = fmaf(w, r1.w, rb[5]);
        rb[6] = fmaf(w, r0.z, rb[6]);
        rb[7] = fmaf(w, r1.y, rb[7]);
        rb[8] = fmaf(w, r2.x, rb[8]);
    }

    const float inv = 1.0f / wsum;
    float o0 = (dis0 > 0.00021f) ? 1000000000.0f : pb0 * inv;
    float* op = out + (long)pt * 3;
    op[0] = o0;
    op[1] = pb1 * inv;
    op[2] = pb2 * inv;
    float* orr = out + (long)N_PTS * 3 + (long)pt * 9;
    #pragma unroll
    for (int i = 0; i < 9; i++) orr[i] = rb[i] * inv;
}

extern "C" void kernel_launch(void* const* d_in, const int* in_sizes, int n_in,
                              void* d_out, int out_size) {
    const float* inputs = (const float*)d_in[0];
    const float* vd     = (const float*)d_in[1];
    const float* R      = (const float*)d_in[2];
    const float* g      = (const float*)d_in[3];
    const float* t      = (const float*)d_in[4];
    float* out = (float*)d_out;

    prep_kernel<<<(N_NODES + 255) / 256, 256>>>(vd, R, g, t);
    zero_bins_kernel<<<NBINS / 256, 256>>>();
    bin_count_kernel<<<N_PTS / 256, 256>>>(inputs);
    scan_bins_kernel<<<1, 1024>>>();
    scatter_kernel<<<N_PTS / 256, 256>>>();
    dg_kernel<<<N_PTS / 128, 128>>>(inputs, out);
}